// round 6
// baseline (speedup 1.0000x reference)
#include <cuda_runtime.h>
#include <cuda_bf16.h>
#include <math.h>

#define NATM 200000
#define NBLK 50000
#define NE   450000
#define NG   64
#define HID  128
#define RAD  64
#define EDGEF 256
#define NLAY 3
#define TABN 2048          // table entries per layer, spacing 1/256 over [0,8)
#define TABSCALE 256.0f

// ---- scratch layout (single __device__ buffer, floats) ----
static const size_t OFF_H     = 0;          // [NBLK*128]
static const size_t OFF_ZC    = 6400000;    // [NBLK*4] z0,z1,z2,cnt
static const size_t OFF_A     = 6600000;    // [NBLK*256]
static const size_t OFF_B     = 19400000;   // [NBLK*256]
static const size_t OFF_AGG   = 32200000;   // [NBLK*256]
static const size_t OFF_TAB   = 45000000;   // [3*2048*256]
static const size_t OFF_WC    = 46572864;   // [3*64*256]
static const size_t OFF_DE    = 46622016;   // [NE]
static const size_t OFF_GACC  = 47072016;   // [64*128]
static const size_t OFF_START = 47080208;   // int[NBLK+1]
static const size_t OFF_CNT   = 47130224;   // int[NBLK] (becomes end offsets)
static const size_t OFF_TOPS  = 47180240;   // int[128]
static const size_t OFF_SSRC  = 47180368;   // int[NE]
static const size_t SCR_TOTAL = 47630368;

__device__ __align__(16) float g_scratch[SCR_TOTAL];

#define NTOPS 98   // ceil(NBLK/512)

__device__ __forceinline__ float silu_f(float x) {
    return x / (1.0f + __expf(-x));
}

__device__ __forceinline__ unsigned cvt_tf32(float f) {
    unsigned u;
    asm("cvt.rna.tf32.f32 %0, %1;" : "=r"(u) : "f"(f));
    return u;
}

__device__ __forceinline__ void mma_tf32(float* c, const unsigned* a,
                                         const unsigned* b) {
    asm volatile(
        "mma.sync.aligned.m16n8k8.row.col.f32.tf32.tf32.f32 "
        "{%0,%1,%2,%3}, {%4,%5,%6,%7}, {%8,%9}, {%0,%1,%2,%3};"
        : "+f"(c[0]), "+f"(c[1]), "+f"(c[2]), "+f"(c[3])
        : "r"(a[0]), "r"(a[1]), "r"(a[2]), "r"(a[3]), "r"(b[0]), "r"(b[1]));
}

__device__ __forceinline__ void red4(float* p, float4 v) {
    asm volatile("red.global.add.v4.f32 [%0], {%1,%2,%3,%4};"
                 :: "l"(p), "f"(v.x), "f"(v.y), "f"(v.z), "f"(v.w)
                 : "memory");
}

// ---------------------------------------------------------------------------
__global__ void k_zero4(float* __restrict__ p, int n4) {
    float4 z = make_float4(0.f, 0.f, 0.f, 0.f);
    for (int i = blockIdx.x * blockDim.x + threadIdx.x; i < n4;
         i += gridDim.x * blockDim.x) {
        ((float4*)p)[i] = z;
    }
}

// ---------------------------------------------------------------------------
// segment boundaries of sorted block_id
// ---------------------------------------------------------------------------
__global__ void k_bounds(const int* __restrict__ bid, int* __restrict__ start) {
    int a = blockIdx.x * blockDim.x + threadIdx.x;
    if (a > NATM) return;
    if (a == 0) {
        int c = bid[0];
        for (int b = 0; b <= c; b++) start[b] = 0;
    } else if (a == NATM) {
        int p = bid[NATM - 1];
        for (int b = p + 1; b <= NBLK; b++) start[b] = NATM;
    } else {
        int p = bid[a - 1], c = bid[a];
        for (int b = p + 1; b <= c; b++) start[b] = a;
    }
}

// ---------------------------------------------------------------------------
// segment-mean pooling: one warp per block
// ---------------------------------------------------------------------------
__global__ void k_pool(const float* __restrict__ H, const float* __restrict__ Z,
                       const int* __restrict__ start, float* __restrict__ h,
                       float* __restrict__ zc, float* __restrict__ outHb) {
    int gt = blockIdx.x * blockDim.x + threadIdx.x;
    int b = gt >> 5;
    int lane = gt & 31;
    if (b >= NBLK) return;
    int lo = start[b], hi = start[b + 1];
    float4 hs = make_float4(0.f, 0.f, 0.f, 0.f);
    for (int a = lo; a < hi; a++) {
        float4 v = *(const float4*)&H[(size_t)a * HID + lane * 4];
        hs.x += v.x; hs.y += v.y; hs.z += v.z; hs.w += v.w;
    }
    float zx = 0.f, zy = 0.f, zz = 0.f;
    for (int a = lo + lane; a < hi; a += 32) {
        zx += Z[a * 3 + 0]; zy += Z[a * 3 + 1]; zz += Z[a * 3 + 2];
    }
#pragma unroll
    for (int o = 16; o > 0; o >>= 1) {
        zx += __shfl_xor_sync(0xffffffffu, zx, o);
        zy += __shfl_xor_sync(0xffffffffu, zy, o);
        zz += __shfl_xor_sync(0xffffffffu, zz, o);
    }
    float cnt = (float)(hi - lo);
    float inv = 1.0f / fmaxf(cnt, 1.0f);
    hs.x *= inv; hs.y *= inv; hs.z *= inv; hs.w *= inv;
    *(float4*)&h[(size_t)b * HID + lane * 4] = hs;
    *(float4*)&outHb[(size_t)b * HID + lane * 4] = hs;
    if (lane == 0) {
        zc[b * 4 + 0] = zx * inv;
        zc[b * 4 + 1] = zy * inv;
        zc[b * 4 + 2] = zz * inv;
        zc[b * 4 + 3] = cnt;
    }
}

// ---------------------------------------------------------------------------
// counting sort of edges by dst (distance computed during scatter)
// ---------------------------------------------------------------------------
__global__ void k_hist(const int* __restrict__ edges, int* __restrict__ cnt) {
    int e = blockIdx.x * blockDim.x + threadIdx.x;
    if (e < NE) atomicAdd(&cnt[edges[NE + e]], 1);
}

__global__ void k_scan1(const int* __restrict__ cnt, int* __restrict__ offs,
                        int* __restrict__ tops) {
    __shared__ int sh[512];
    int i = blockIdx.x * 512 + threadIdx.x;
    int v = (i < NBLK) ? cnt[i] : 0;
    sh[threadIdx.x] = v;
    __syncthreads();
#pragma unroll
    for (int off = 1; off < 512; off <<= 1) {
        int t = 0;
        if (threadIdx.x >= off) t = sh[threadIdx.x - off];
        __syncthreads();
        if (threadIdx.x >= off) sh[threadIdx.x] += t;
        __syncthreads();
    }
    if (i < NBLK) offs[i] = sh[threadIdx.x] - v;
    if (threadIdx.x == 511) tops[blockIdx.x] = sh[511];
}

__global__ void k_scan2(int* __restrict__ tops) {
    __shared__ int sh[128];
    int v = (threadIdx.x < NTOPS) ? tops[threadIdx.x] : 0;
    sh[threadIdx.x] = v;
    __syncthreads();
#pragma unroll
    for (int off = 1; off < 128; off <<= 1) {
        int t = 0;
        if (threadIdx.x >= off) t = sh[threadIdx.x - off];
        __syncthreads();
        if (threadIdx.x >= off) sh[threadIdx.x] += t;
        __syncthreads();
    }
    if (threadIdx.x < NTOPS) tops[threadIdx.x] = sh[threadIdx.x] - v;
}

__global__ void k_scan3(int* __restrict__ offs, const int* __restrict__ tops) {
    int i = blockIdx.x * 512 + threadIdx.x;
    if (i < NBLK) offs[i] += tops[blockIdx.x];
}

// scatter + per-edge distance in sorted position
__global__ void k_scat(const int* __restrict__ edges, int* __restrict__ offs,
                       const float* __restrict__ zc, int* __restrict__ ssrc,
                       float* __restrict__ de) {
    int e = blockIdx.x * blockDim.x + threadIdx.x;
    if (e >= NE) return;
    int s = edges[e];
    int d = edges[NE + e];
    int pos = atomicAdd(&offs[d], 1);
    float dx = zc[s * 4 + 0] - zc[d * 4 + 0];
    float dy = zc[s * 4 + 1] - zc[d * 4 + 1];
    float dz = zc[s * 4 + 2] - zc[d * 4 + 2];
    ssrc[pos] = s;
    de[pos] = sqrtf(dx * dx + dy * dy + dz * dz + 1e-12f);
}
// after k_scat, offs[d] holds the END offset of dst-segment d.

// ---------------------------------------------------------------------------
// build lookup table T[l][g][j] = rbf(g/256) @ Wc[l]
// grid (TABN/4, 3), 256 threads; 4 grid points share each W read.
// ---------------------------------------------------------------------------
__global__ void k_table(const float* __restrict__ Wc, float* __restrict__ T) {
    __shared__ float rb[4][64];
    int g0 = blockIdx.x * 4, l = blockIdx.y;
    int tid = threadIdx.x;
    {
        int gi = tid >> 6;      // 0..3
        int k = tid & 63;
        float dd = (float)(g0 + gi) * (1.0f / TABSCALE)
                 - (6.0f / 63.0f) * (float)k;
        rb[gi][k] = __expf(-10.0f * dd * dd);
    }
    __syncthreads();
    const float* W = Wc + (size_t)l * 64 * 256;
    float acc0 = 0.f, acc1 = 0.f, acc2 = 0.f, acc3 = 0.f;
#pragma unroll 16
    for (int k = 0; k < 64; k++) {
        float w = W[k * 256 + tid];
        acc0 += rb[0][k] * w;
        acc1 += rb[1][k] * w;
        acc2 += rb[2][k] * w;
        acc3 += rb[3][k] * w;
    }
    float* out = T + ((size_t)l * TABN + g0) * 256 + tid;
    out[0]   = acc0;
    out[256] = acc1;
    out[512] = acc2;
    out[768] = acc3;
}

// ---------------------------------------------------------------------------
// tf32 tensor GEMM, double-buffered, compile-time K.
// BM=128 BN=64 BK=32, 256 threads. block.x >= ntiles0 -> (B1,C1).
// EPI==1: C += silu(acc). Requires N%64==0.
// ---------------------------------------------------------------------------
template <int K, int EPI>
__global__ void __launch_bounds__(256)
k_gemm(const float* __restrict__ A, const float* __restrict__ B0,
       const float* __restrict__ B1, float* __restrict__ C0,
       float* __restrict__ C1, int M, int N, int ntiles0) {
    __shared__ unsigned As[128 * 36];
    __shared__ unsigned Bs[32 * 68];
    int tid = threadIdx.x;
    int warp = tid >> 5, lane = tid & 31;
    int gid = lane >> 2, tig = lane & 3;
    int wm = (warp & 3) * 32, wn = (warp >> 2) * 32;
    int rowBase = blockIdx.y * 128;
    int bx = blockIdx.x;
    const float* B = B0;
    float* C = C0;
    if (bx >= ntiles0) { B = B1; C = C1; bx -= ntiles0; }
    int colBase = bx * 64;

    int ar = tid >> 3, ac = (tid & 7) * 4;
    int br = tid >> 4, bc = (tid & 15) * 4;

    float4 av[4], bv[2];
#pragma unroll
    for (int i = 0; i < 4; i++) {
        int r = rowBase + ar + i * 32;
        av[i] = (r < M) ? *(const float4*)&A[(size_t)r * K + ac]
                        : make_float4(0.f, 0.f, 0.f, 0.f);
    }
#pragma unroll
    for (int i = 0; i < 2; i++)
        bv[i] = *(const float4*)&B[(size_t)(br + i * 16) * N + colBase + bc];

    float acc[2][4][4];
#pragma unroll
    for (int mt = 0; mt < 2; mt++)
#pragma unroll
        for (int nn = 0; nn < 4; nn++)
#pragma unroll
            for (int q = 0; q < 4; q++) acc[mt][nn][q] = 0.f;

#pragma unroll
    for (int k0 = 0; k0 < K; k0 += 32) {
#pragma unroll
        for (int i = 0; i < 4; i++) {
            uint4 u;
            u.x = cvt_tf32(av[i].x); u.y = cvt_tf32(av[i].y);
            u.z = cvt_tf32(av[i].z); u.w = cvt_tf32(av[i].w);
            *(uint4*)&As[(ar + i * 32) * 36 + ac] = u;
        }
#pragma unroll
        for (int i = 0; i < 2; i++) {
            uint4 u;
            u.x = cvt_tf32(bv[i].x); u.y = cvt_tf32(bv[i].y);
            u.z = cvt_tf32(bv[i].z); u.w = cvt_tf32(bv[i].w);
            *(uint4*)&Bs[(br + i * 16) * 68 + bc] = u;
        }
        __syncthreads();
        if (k0 + 32 < K) {
#pragma unroll
            for (int i = 0; i < 4; i++) {
                int r = rowBase + ar + i * 32;
                av[i] = (r < M)
                    ? *(const float4*)&A[(size_t)r * K + k0 + 32 + ac]
                    : make_float4(0.f, 0.f, 0.f, 0.f);
            }
#pragma unroll
            for (int i = 0; i < 2; i++)
                bv[i] = *(const float4*)
                    &B[(size_t)(k0 + 32 + br + i * 16) * N + colBase + bc];
        }
#pragma unroll
        for (int kk = 0; kk < 4; kk++) {
            unsigned a[2][4], b[4][2];
#pragma unroll
            for (int mt = 0; mt < 2; mt++) {
                int r = wm + mt * 16 + gid;
                a[mt][0] = As[r * 36 + kk * 8 + tig];
                a[mt][1] = As[(r + 8) * 36 + kk * 8 + tig];
                a[mt][2] = As[r * 36 + kk * 8 + tig + 4];
                a[mt][3] = As[(r + 8) * 36 + kk * 8 + tig + 4];
            }
#pragma unroll
            for (int nn = 0; nn < 4; nn++) {
                b[nn][0] = Bs[(kk * 8 + tig) * 68 + wn + nn * 8 + gid];
                b[nn][1] = Bs[(kk * 8 + tig + 4) * 68 + wn + nn * 8 + gid];
            }
#pragma unroll
            for (int mt = 0; mt < 2; mt++)
#pragma unroll
                for (int nn = 0; nn < 4; nn++)
                    mma_tf32(acc[mt][nn], a[mt], b[nn]);
        }
        __syncthreads();
    }

#pragma unroll
    for (int mt = 0; mt < 2; mt++) {
#pragma unroll
        for (int nn = 0; nn < 4; nn++) {
            int r0 = rowBase + wm + mt * 16 + gid;
            int r1 = r0 + 8;
            int c = colBase + wn + nn * 8 + 2 * tig;
            if (r0 < M) {
                size_t idx = (size_t)r0 * N + c;
                if (EPI == 1) {
                    C[idx]     += silu_f(acc[mt][nn][0]);
                    C[idx + 1] += silu_f(acc[mt][nn][1]);
                } else {
                    C[idx]     = acc[mt][nn][0];
                    C[idx + 1] = acc[mt][nn][1];
                }
            }
            if (r1 < M) {
                size_t idx = (size_t)r1 * N + c;
                if (EPI == 1) {
                    C[idx]     += silu_f(acc[mt][nn][2]);
                    C[idx + 1] += silu_f(acc[mt][nn][3]);
                } else {
                    C[idx]     = acc[mt][nn][2];
                    C[idx + 1] = acc[mt][nn][3];
                }
            }
        }
    }
}

// ---------------------------------------------------------------------------
// edge+aggregate kernel: one warp per dst block, software-pipelined.
// agg[d] = sum_{e in seg(d)} silu(A[src_e] + B[d] + lerp(T, de[e]))
// ---------------------------------------------------------------------------
__global__ void __launch_bounds__(256)
k_edge_lut(const int* __restrict__ ssrc, const int* __restrict__ eend,
           const float* __restrict__ Tl, const float* __restrict__ de,
           const float* __restrict__ Ag, const float* __restrict__ Bg,
           float* __restrict__ agg) {
    int gt = blockIdx.x * blockDim.x + threadIdx.x;
    int d = gt >> 5;
    int lane = gt & 31;
    if (d >= NBLK) return;
    int lo = (d > 0) ? eend[d - 1] : 0;
    int hi = eend[d];
    int c0 = lane * 4;
    int c1 = 128 + lane * 4;

    float4 acc0 = make_float4(0.f, 0.f, 0.f, 0.f);
    float4 acc1 = make_float4(0.f, 0.f, 0.f, 0.f);

    if (lo < hi) {
        float4 b0 = *(const float4*)&Bg[(size_t)d * 256 + c0];
        float4 b1 = *(const float4*)&Bg[(size_t)d * 256 + c1];
        const float maxT = (float)(TABN - 2) + 0.999f;

        // prologue: load everything for edge lo
        float4 a0, a1, u00, u01, u10, u11;
        float ff;
        {
            int s = ssrc[lo];
            float t = fminf(de[lo] * TABSCALE, maxT);
            int it = (int)t;
            ff = t - (float)it;
            const float* r0 = Tl + (size_t)it * 256;
            a0 = *(const float4*)&Ag[(size_t)s * 256 + c0];
            a1 = *(const float4*)&Ag[(size_t)s * 256 + c1];
            u00 = *(const float4*)&r0[c0];
            u01 = *(const float4*)&r0[c1];
            u10 = *(const float4*)&r0[256 + c0];
            u11 = *(const float4*)&r0[256 + c1];
        }

        for (int e = lo; e < hi; e++) {
            // capture current
            float4 ca0 = a0, ca1 = a1;
            float4 cu00 = u00, cu01 = u01, cu10 = u10, cu11 = u11;
            float cf = ff;
            // issue next edge's loads (overlap with compute below)
            if (e + 1 < hi) {
                int s = ssrc[e + 1];
                float t = fminf(de[e + 1] * TABSCALE, maxT);
                int it = (int)t;
                ff = t - (float)it;
                const float* r0 = Tl + (size_t)it * 256;
                a0 = *(const float4*)&Ag[(size_t)s * 256 + c0];
                a1 = *(const float4*)&Ag[(size_t)s * 256 + c1];
                u00 = *(const float4*)&r0[c0];
                u01 = *(const float4*)&r0[c1];
                u10 = *(const float4*)&r0[256 + c0];
                u11 = *(const float4*)&r0[256 + c1];
            }
            // compute current
            acc0.x += silu_f(ca0.x + b0.x + cu00.x + cf * (cu10.x - cu00.x));
            acc0.y += silu_f(ca0.y + b0.y + cu00.y + cf * (cu10.y - cu00.y));
            acc0.z += silu_f(ca0.z + b0.z + cu00.z + cf * (cu10.z - cu00.z));
            acc0.w += silu_f(ca0.w + b0.w + cu00.w + cf * (cu10.w - cu00.w));
            acc1.x += silu_f(ca1.x + b1.x + cu01.x + cf * (cu11.x - cu01.x));
            acc1.y += silu_f(ca1.y + b1.y + cu01.y + cf * (cu11.y - cu01.y));
            acc1.z += silu_f(ca1.z + b1.z + cu01.z + cf * (cu11.z - cu01.z));
            acc1.w += silu_f(ca1.w + b1.w + cu01.w + cf * (cu11.w - cu01.w));
        }
    }
    *(float4*)&agg[(size_t)d * 256 + c0] = acc0;
    *(float4*)&agg[(size_t)d * 256 + c1] = acc1;
}

// ---------------------------------------------------------------------------
__global__ void k_rownorm_scatter(const float* __restrict__ tmp,
                                  const int* __restrict__ batch_id,
                                  float* __restrict__ out_block,
                                  float* __restrict__ gacc) {
    int gt = blockIdx.x * blockDim.x + threadIdx.x;
    int r = gt >> 5;
    int lane = gt & 31;
    if (r >= NBLK) return;
    float4 v = *(const float4*)&tmp[(size_t)r * HID + lane * 4];
    float ss = v.x * v.x + v.y * v.y + v.z * v.z + v.w * v.w;
#pragma unroll
    for (int o = 16; o > 0; o >>= 1) ss += __shfl_xor_sync(0xffffffffu, ss, o);
    float inv = 1.0f / fmaxf(sqrtf(ss), 1e-12f);
    int g = batch_id[r];
    float4 nv = make_float4(v.x * inv, v.y * inv, v.z * inv, v.w * inv);
    *(float4*)&out_block[(size_t)r * HID + lane * 4] = nv;
    red4(&gacc[g * HID + lane * 4], nv);
}

__global__ void k_graphnorm(const float* __restrict__ gacc,
                            float* __restrict__ out_graph) {
    int gt = blockIdx.x * blockDim.x + threadIdx.x;
    int r = gt >> 5;
    int lane = gt & 31;
    if (r >= NG) return;
    float4 v = *(const float4*)&gacc[r * HID + lane * 4];
    float ss = v.x * v.x + v.y * v.y + v.z * v.z + v.w * v.w;
#pragma unroll
    for (int o = 16; o > 0; o >>= 1) ss += __shfl_xor_sync(0xffffffffu, ss, o);
    float inv = 1.0f / fmaxf(sqrtf(ss), 1e-12f);
    float4 nv = make_float4(v.x * inv, v.y * inv, v.z * inv, v.w * inv);
    *(float4*)&out_graph[r * HID + lane * 4] = nv;
}

// ---------------------------------------------------------------------------
extern "C" void kernel_launch(void* const* d_in, const int* in_sizes, int n_in,
                              void* d_out, int out_size) {
    const float* H      = (const float*)d_in[0];
    const float* Z      = (const float*)d_in[1];
    const float* W_rbf  = (const float*)d_in[2];
    const float* Wm1    = (const float*)d_in[3];
    const float* Wm2    = (const float*)d_in[4];
    const float* We     = (const float*)d_in[5];
    const float* Wupd   = (const float*)d_in[6];
    const float* W_out  = (const float*)d_in[7];
    const int*   block_id = (const int*)d_in[8];
    const int*   batch_id = (const int*)d_in[9];
    const int*   edges    = (const int*)d_in[10];

    float* out = (float*)d_out;
    float* out_Hb    = out;
    float* out_block = out + (size_t)NBLK * HID;
    float* out_graph = out + 2 * (size_t)NBLK * HID;

    void* scrv = nullptr;
    cudaGetSymbolAddress(&scrv, g_scratch);
    float* scr  = (float*)scrv;
    float* s_h    = scr + OFF_H;
    float* s_zc   = scr + OFF_ZC;
    float* s_A    = scr + OFF_A;
    float* s_B    = scr + OFF_B;
    float* s_agg  = scr + OFF_AGG;
    float* s_tab  = scr + OFF_TAB;
    float* s_Wc   = scr + OFF_WC;
    float* s_de   = scr + OFF_DE;
    float* s_gacc = scr + OFF_GACC;
    int*   s_start = (int*)(scr + OFF_START);
    int*   s_cnt   = (int*)(scr + OFF_CNT);
    int*   s_tops  = (int*)(scr + OFF_TOPS);
    int*   s_ssrc  = (int*)(scr + OFF_SSRC);

    // Wc[l] = W_rbf @ We[l], then build interpolation table
    for (int l = 0; l < NLAY; l++) {
        k_gemm<256, 0><<<dim3(4, 1), 256>>>(
            W_rbf, We + (size_t)l * 256 * 256, nullptr,
            s_Wc + (size_t)l * 64 * 256, nullptr, 64, 256, 4);
    }
    k_table<<<dim3(TABN / 4, NLAY), 256>>>(s_Wc, s_tab);

    // pooling via sorted segments
    k_bounds<<<(NATM + 256) / 256, 256>>>(block_id, s_start);
    k_pool<<<(NBLK * 32 + 255) / 256, 256>>>(H, Z, s_start, s_h, s_zc, out_Hb);

    // counting sort of edges by dst (s_cnt ends as END offsets); dist fused
    k_zero4<<<32, 256>>>((float*)s_cnt, 50016 / 4);
    k_hist<<<(NE + 255) / 256, 256>>>(edges, s_cnt);
    k_scan1<<<NTOPS, 512>>>(s_cnt, s_cnt, s_tops);
    k_scan2<<<1, 128>>>(s_tops);
    k_scan3<<<NTOPS, 512>>>(s_cnt, s_tops);
    k_scat<<<(NE + 255) / 256, 256>>>(edges, s_cnt, s_zc, s_ssrc, s_de);

    // zero graph accumulator
    k_zero4<<<8, 256>>>(s_gacc, (NG * HID) / 4);

    dim3 gridAB(8, (NBLK + 127) / 128);
    dim3 gridUpd(2, (NBLK + 127) / 128);

    for (int l = 0; l < NLAY; l++) {
        // A = h@Wm1[l], B = h@Wm2[l] in one launch
        k_gemm<128, 0><<<gridAB, 256>>>(
            s_h, Wm1 + (size_t)l * HID * EDGEF, Wm2 + (size_t)l * HID * EDGEF,
            s_A, s_B, NBLK, EDGEF, 4);
        // fused edge messages + per-dst aggregation (plain stores)
        k_edge_lut<<<(NBLK * 32 + 255) / 256, 256>>>(
            s_ssrc, s_cnt, s_tab + (size_t)l * TABN * 256, s_de, s_A, s_B,
            s_agg);
        // h = h + silu(agg @ Wupd[l])
        k_gemm<256, 1><<<gridUpd, 256>>>(
            s_agg, Wupd + (size_t)l * EDGEF * HID, nullptr, s_h, nullptr,
            NBLK, HID, 2);
    }

    // block_repr = l2norm(h @ W_out)
    k_gemm<128, 0><<<gridUpd, 256>>>(s_h, W_out, nullptr, s_A, nullptr,
                                     NBLK, HID, 2);
    k_rownorm_scatter<<<(NBLK * 32 + 255) / 256, 256>>>(s_A, batch_id,
                                                        out_block, s_gacc);
    k_graphnorm<<<(NG * 32 + 255) / 256, 256>>>(s_gacc, out_graph);
}

// round 7
// speedup vs baseline: 1.1819x; 1.1819x over previous
#include <cuda_runtime.h>
#include <cuda_bf16.h>
#include <math.h>

#define NATM 200000
#define NBLK 50000
#define NE   450000
#define NG   64
#define HID  128
#define RAD  64
#define EDGEF 256
#define NLAY 3
#define TABN 2048          // table entries per layer, spacing 1/256 over [0,8)
#define TABSCALE 256.0f

// ---- scratch layout (single __device__ buffer, floats) ----
static const size_t OFF_H     = 0;          // [NBLK*128]
static const size_t OFF_ZC    = 6400000;    // [NBLK*4] z0,z1,z2,cnt
static const size_t OFF_A     = 6600000;    // [NBLK*256]
static const size_t OFF_B     = 19400000;   // [NBLK*256]
static const size_t OFF_AGG   = 32200000;   // [NBLK*256]
static const size_t OFF_TAB   = 45000000;   // [3*2048*256]
static const size_t OFF_WC    = 46572864;   // [3*64*256]
static const size_t OFF_DE    = 46622016;   // [NE]
static const size_t OFF_GACC  = 47072016;   // [64*128]
static const size_t OFF_START = 47080208;   // int[NBLK+1]
static const size_t OFF_CNT   = 47130224;   // int[NBLK] (becomes end offsets)
static const size_t OFF_TOPS  = 47180240;   // int[128]
static const size_t OFF_SSRC  = 47180368;   // int[NE]
static const size_t SCR_TOTAL = 47630368;

__device__ __align__(16) float g_scratch[SCR_TOTAL];

#define NTOPS 98   // ceil(NBLK/512)

__device__ __forceinline__ float silu_f(float x) {
    return x / (1.0f + __expf(-x));
}

__device__ __forceinline__ unsigned cvt_tf32(float f) {
    unsigned u;
    asm("cvt.rna.tf32.f32 %0, %1;" : "=r"(u) : "f"(f));
    return u;
}

__device__ __forceinline__ void mma_tf32(float* c, const unsigned* a,
                                         const unsigned* b) {
    asm volatile(
        "mma.sync.aligned.m16n8k8.row.col.f32.tf32.tf32.f32 "
        "{%0,%1,%2,%3}, {%4,%5,%6,%7}, {%8,%9}, {%0,%1,%2,%3};"
        : "+f"(c[0]), "+f"(c[1]), "+f"(c[2]), "+f"(c[3])
        : "r"(a[0]), "r"(a[1]), "r"(a[2]), "r"(a[3]), "r"(b[0]), "r"(b[1]));
}

__device__ __forceinline__ void red4(float* p, float4 v) {
    asm volatile("red.global.add.v4.f32 [%0], {%1,%2,%3,%4};"
                 :: "l"(p), "f"(v.x), "f"(v.y), "f"(v.z), "f"(v.w)
                 : "memory");
}

// ---------------------------------------------------------------------------
__global__ void k_zero4(float* __restrict__ p, int n4) {
    float4 z = make_float4(0.f, 0.f, 0.f, 0.f);
    for (int i = blockIdx.x * blockDim.x + threadIdx.x; i < n4;
         i += gridDim.x * blockDim.x) {
        ((float4*)p)[i] = z;
    }
}

// ---------------------------------------------------------------------------
// segment boundaries of sorted block_id
// ---------------------------------------------------------------------------
__global__ void k_bounds(const int* __restrict__ bid, int* __restrict__ start) {
    int a = blockIdx.x * blockDim.x + threadIdx.x;
    if (a > NATM) return;
    if (a == 0) {
        int c = bid[0];
        for (int b = 0; b <= c; b++) start[b] = 0;
    } else if (a == NATM) {
        int p = bid[NATM - 1];
        for (int b = p + 1; b <= NBLK; b++) start[b] = NATM;
    } else {
        int p = bid[a - 1], c = bid[a];
        for (int b = p + 1; b <= c; b++) start[b] = a;
    }
}

// ---------------------------------------------------------------------------
// segment-mean pooling: one warp per block
// ---------------------------------------------------------------------------
__global__ void k_pool(const float* __restrict__ H, const float* __restrict__ Z,
                       const int* __restrict__ start, float* __restrict__ h,
                       float* __restrict__ zc, float* __restrict__ outHb) {
    int gt = blockIdx.x * blockDim.x + threadIdx.x;
    int b = gt >> 5;
    int lane = gt & 31;
    if (b >= NBLK) return;
    int lo = start[b], hi = start[b + 1];
    float4 hs = make_float4(0.f, 0.f, 0.f, 0.f);
    for (int a = lo; a < hi; a++) {
        float4 v = *(const float4*)&H[(size_t)a * HID + lane * 4];
        hs.x += v.x; hs.y += v.y; hs.z += v.z; hs.w += v.w;
    }
    float zx = 0.f, zy = 0.f, zz = 0.f;
    for (int a = lo + lane; a < hi; a += 32) {
        zx += Z[a * 3 + 0]; zy += Z[a * 3 + 1]; zz += Z[a * 3 + 2];
    }
#pragma unroll
    for (int o = 16; o > 0; o >>= 1) {
        zx += __shfl_xor_sync(0xffffffffu, zx, o);
        zy += __shfl_xor_sync(0xffffffffu, zy, o);
        zz += __shfl_xor_sync(0xffffffffu, zz, o);
    }
    float cnt = (float)(hi - lo);
    float inv = 1.0f / fmaxf(cnt, 1.0f);
    hs.x *= inv; hs.y *= inv; hs.z *= inv; hs.w *= inv;
    *(float4*)&h[(size_t)b * HID + lane * 4] = hs;
    *(float4*)&outHb[(size_t)b * HID + lane * 4] = hs;
    if (lane == 0) {
        zc[b * 4 + 0] = zx * inv;
        zc[b * 4 + 1] = zy * inv;
        zc[b * 4 + 2] = zz * inv;
        zc[b * 4 + 3] = cnt;
    }
}

// ---------------------------------------------------------------------------
// counting sort of edges by dst (distance computed during scatter)
// ---------------------------------------------------------------------------
__global__ void k_hist(const int* __restrict__ edges, int* __restrict__ cnt) {
    int e = blockIdx.x * blockDim.x + threadIdx.x;
    if (e < NE) atomicAdd(&cnt[edges[NE + e]], 1);
}

__global__ void k_scan1(const int* __restrict__ cnt, int* __restrict__ offs,
                        int* __restrict__ tops) {
    __shared__ int sh[512];
    int i = blockIdx.x * 512 + threadIdx.x;
    int v = (i < NBLK) ? cnt[i] : 0;
    sh[threadIdx.x] = v;
    __syncthreads();
#pragma unroll
    for (int off = 1; off < 512; off <<= 1) {
        int t = 0;
        if (threadIdx.x >= off) t = sh[threadIdx.x - off];
        __syncthreads();
        if (threadIdx.x >= off) sh[threadIdx.x] += t;
        __syncthreads();
    }
    if (i < NBLK) offs[i] = sh[threadIdx.x] - v;
    if (threadIdx.x == 511) tops[blockIdx.x] = sh[511];
}

__global__ void k_scan2(int* __restrict__ tops) {
    __shared__ int sh[128];
    int v = (threadIdx.x < NTOPS) ? tops[threadIdx.x] : 0;
    sh[threadIdx.x] = v;
    __syncthreads();
#pragma unroll
    for (int off = 1; off < 128; off <<= 1) {
        int t = 0;
        if (threadIdx.x >= off) t = sh[threadIdx.x - off];
        __syncthreads();
        if (threadIdx.x >= off) sh[threadIdx.x] += t;
        __syncthreads();
    }
    if (threadIdx.x < NTOPS) tops[threadIdx.x] = sh[threadIdx.x] - v;
}

__global__ void k_scan3(int* __restrict__ offs, const int* __restrict__ tops) {
    int i = blockIdx.x * 512 + threadIdx.x;
    if (i < NBLK) offs[i] += tops[blockIdx.x];
}

// scatter + per-edge distance in sorted position
__global__ void k_scat(const int* __restrict__ edges, int* __restrict__ offs,
                       const float* __restrict__ zc, int* __restrict__ ssrc,
                       float* __restrict__ de) {
    int e = blockIdx.x * blockDim.x + threadIdx.x;
    if (e >= NE) return;
    int s = edges[e];
    int d = edges[NE + e];
    int pos = atomicAdd(&offs[d], 1);
    float dx = zc[s * 4 + 0] - zc[d * 4 + 0];
    float dy = zc[s * 4 + 1] - zc[d * 4 + 1];
    float dz = zc[s * 4 + 2] - zc[d * 4 + 2];
    ssrc[pos] = s;
    de[pos] = sqrtf(dx * dx + dy * dy + dz * dz + 1e-12f);
}
// after k_scat, offs[d] holds the END offset of dst-segment d.

// ---------------------------------------------------------------------------
// build lookup table T[l][g][j] = rbf(g/256) @ Wc[l]
// grid (TABN/4, 3), 256 threads; 4 grid points share each W read.
// ---------------------------------------------------------------------------
__global__ void k_table(const float* __restrict__ Wc, float* __restrict__ T) {
    __shared__ float rb[4][64];
    int g0 = blockIdx.x * 4, l = blockIdx.y;
    int tid = threadIdx.x;
    {
        int gi = tid >> 6;      // 0..3
        int k = tid & 63;
        float dd = (float)(g0 + gi) * (1.0f / TABSCALE)
                 - (6.0f / 63.0f) * (float)k;
        rb[gi][k] = __expf(-10.0f * dd * dd);
    }
    __syncthreads();
    const float* W = Wc + (size_t)l * 64 * 256;
    float acc0 = 0.f, acc1 = 0.f, acc2 = 0.f, acc3 = 0.f;
#pragma unroll 16
    for (int k = 0; k < 64; k++) {
        float w = W[k * 256 + tid];
        acc0 += rb[0][k] * w;
        acc1 += rb[1][k] * w;
        acc2 += rb[2][k] * w;
        acc3 += rb[3][k] * w;
    }
    float* out = T + ((size_t)l * TABN + g0) * 256 + tid;
    out[0]   = acc0;
    out[256] = acc1;
    out[512] = acc2;
    out[768] = acc3;
}

// ---------------------------------------------------------------------------
// tf32 tensor GEMM, double-buffered: C[M,N] = A[M,K] @ B[K,N]
// BM=128 BN=64 BK=32, 256 threads. block.x >= ntiles0 -> (B1,C1).
// epi==1: C += silu(acc). Requires K%32==0, N%64==0.
// ---------------------------------------------------------------------------
__global__ void __launch_bounds__(256)
k_gemm(const float* __restrict__ A, const float* __restrict__ B0,
       const float* __restrict__ B1, float* __restrict__ C0,
       float* __restrict__ C1, int M, int N, int K, int epi, int ntiles0) {
    __shared__ unsigned As[128 * 36];
    __shared__ unsigned Bs[32 * 68];
    int tid = threadIdx.x;
    int warp = tid >> 5, lane = tid & 31;
    int gid = lane >> 2, tig = lane & 3;
    int wm = (warp & 3) * 32, wn = (warp >> 2) * 32;
    int rowBase = blockIdx.y * 128;
    int bx = blockIdx.x;
    const float* B = B0;
    float* C = C0;
    if (bx >= ntiles0) { B = B1; C = C1; bx -= ntiles0; }
    int colBase = bx * 64;

    int ar = tid >> 3, ac = (tid & 7) * 4;
    int br = tid >> 4, bc = (tid & 15) * 4;

    float4 av[4], bv[2];
#pragma unroll
    for (int i = 0; i < 4; i++) {
        int r = rowBase + ar + i * 32;
        av[i] = (r < M) ? *(const float4*)&A[(size_t)r * K + ac]
                        : make_float4(0.f, 0.f, 0.f, 0.f);
    }
#pragma unroll
    for (int i = 0; i < 2; i++)
        bv[i] = *(const float4*)&B[(size_t)(br + i * 16) * N + colBase + bc];

    float acc[2][4][4];
#pragma unroll
    for (int mt = 0; mt < 2; mt++)
#pragma unroll
        for (int nn = 0; nn < 4; nn++)
#pragma unroll
            for (int q = 0; q < 4; q++) acc[mt][nn][q] = 0.f;

    for (int k0 = 0; k0 < K; k0 += 32) {
#pragma unroll
        for (int i = 0; i < 4; i++) {
            uint4 u;
            u.x = cvt_tf32(av[i].x); u.y = cvt_tf32(av[i].y);
            u.z = cvt_tf32(av[i].z); u.w = cvt_tf32(av[i].w);
            *(uint4*)&As[(ar + i * 32) * 36 + ac] = u;
        }
#pragma unroll
        for (int i = 0; i < 2; i++) {
            uint4 u;
            u.x = cvt_tf32(bv[i].x); u.y = cvt_tf32(bv[i].y);
            u.z = cvt_tf32(bv[i].z); u.w = cvt_tf32(bv[i].w);
            *(uint4*)&Bs[(br + i * 16) * 68 + bc] = u;
        }
        __syncthreads();
        if (k0 + 32 < K) {
#pragma unroll
            for (int i = 0; i < 4; i++) {
                int r = rowBase + ar + i * 32;
                av[i] = (r < M)
                    ? *(const float4*)&A[(size_t)r * K + k0 + 32 + ac]
                    : make_float4(0.f, 0.f, 0.f, 0.f);
            }
#pragma unroll
            for (int i = 0; i < 2; i++)
                bv[i] = *(const float4*)
                    &B[(size_t)(k0 + 32 + br + i * 16) * N + colBase + bc];
        }
#pragma unroll
        for (int kk = 0; kk < 4; kk++) {
            unsigned a[2][4], b[4][2];
#pragma unroll
            for (int mt = 0; mt < 2; mt++) {
                int r = wm + mt * 16 + gid;
                a[mt][0] = As[r * 36 + kk * 8 + tig];
                a[mt][1] = As[(r + 8) * 36 + kk * 8 + tig];
                a[mt][2] = As[r * 36 + kk * 8 + tig + 4];
                a[mt][3] = As[(r + 8) * 36 + kk * 8 + tig + 4];
            }
#pragma unroll
            for (int nn = 0; nn < 4; nn++) {
                b[nn][0] = Bs[(kk * 8 + tig) * 68 + wn + nn * 8 + gid];
                b[nn][1] = Bs[(kk * 8 + tig + 4) * 68 + wn + nn * 8 + gid];
            }
#pragma unroll
            for (int mt = 0; mt < 2; mt++)
#pragma unroll
                for (int nn = 0; nn < 4; nn++)
                    mma_tf32(acc[mt][nn], a[mt], b[nn]);
        }
        __syncthreads();
    }

#pragma unroll
    for (int mt = 0; mt < 2; mt++) {
#pragma unroll
        for (int nn = 0; nn < 4; nn++) {
            int r0 = rowBase + wm + mt * 16 + gid;
            int r1 = r0 + 8;
            int c = colBase + wn + nn * 8 + 2 * tig;
            if (r0 < M) {
                size_t idx = (size_t)r0 * N + c;
                if (epi == 1) {
                    C[idx]     += silu_f(acc[mt][nn][0]);
                    C[idx + 1] += silu_f(acc[mt][nn][1]);
                } else {
                    C[idx]     = acc[mt][nn][0];
                    C[idx + 1] = acc[mt][nn][1];
                }
            }
            if (r1 < M) {
                size_t idx = (size_t)r1 * N + c;
                if (epi == 1) {
                    C[idx]     += silu_f(acc[mt][nn][2]);
                    C[idx + 1] += silu_f(acc[mt][nn][3]);
                } else {
                    C[idx]     = acc[mt][nn][2];
                    C[idx + 1] = acc[mt][nn][3];
                }
            }
        }
    }
}

// ---------------------------------------------------------------------------
// edge+aggregate kernel: one warp per dst block (R5 form — compiler-scheduled).
// agg[d] = sum_{e in seg(d)} silu(A[src_e] + B[d] + lerp(T, de[e]))
// Plain stores (no atomics, no pre-zero). Table rows hot in L2.
// ---------------------------------------------------------------------------
__global__ void __launch_bounds__(256)
k_edge_lut(const int* __restrict__ ssrc, const int* __restrict__ eend,
           const float* __restrict__ Tl, const float* __restrict__ de,
           const float* __restrict__ Ag, const float* __restrict__ Bg,
           float* __restrict__ agg) {
    int gt = blockIdx.x * blockDim.x + threadIdx.x;
    int d = gt >> 5;
    int lane = gt & 31;
    if (d >= NBLK) return;
    int lo = (d > 0) ? eend[d - 1] : 0;
    int hi = eend[d];
    int c0 = lane * 4;
    int c1 = 128 + lane * 4;

    float4 acc0 = make_float4(0.f, 0.f, 0.f, 0.f);
    float4 acc1 = make_float4(0.f, 0.f, 0.f, 0.f);

    if (lo < hi) {
        float4 b0 = *(const float4*)&Bg[(size_t)d * 256 + c0];
        float4 b1 = *(const float4*)&Bg[(size_t)d * 256 + c1];
        const float maxT = (float)(TABN - 2) + 0.999f;
        for (int e = lo; e < hi; e++) {
            int s = ssrc[e];
            float t = fminf(de[e] * TABSCALE, maxT);
            int it = (int)t;
            float f = t - (float)it;
            const float* r0 = Tl + (size_t)it * 256;
            const float* r1 = r0 + 256;
            float4 a0 = *(const float4*)&Ag[(size_t)s * 256 + c0];
            float4 a1 = *(const float4*)&Ag[(size_t)s * 256 + c1];
            float4 u00 = *(const float4*)&r0[c0];
            float4 u01 = *(const float4*)&r0[c1];
            float4 u10 = *(const float4*)&r1[c0];
            float4 u11 = *(const float4*)&r1[c1];
            acc0.x += silu_f(a0.x + b0.x + u00.x + f * (u10.x - u00.x));
            acc0.y += silu_f(a0.y + b0.y + u00.y + f * (u10.y - u00.y));
            acc0.z += silu_f(a0.z + b0.z + u00.z + f * (u10.z - u00.z));
            acc0.w += silu_f(a0.w + b0.w + u00.w + f * (u10.w - u00.w));
            acc1.x += silu_f(a1.x + b1.x + u01.x + f * (u11.x - u01.x));
            acc1.y += silu_f(a1.y + b1.y + u01.y + f * (u11.y - u01.y));
            acc1.z += silu_f(a1.z + b1.z + u01.z + f * (u11.z - u01.z));
            acc1.w += silu_f(a1.w + b1.w + u01.w + f * (u11.w - u01.w));
        }
    }
    *(float4*)&agg[(size_t)d * 256 + c0] = acc0;
    *(float4*)&agg[(size_t)d * 256 + c1] = acc1;
}

// ---------------------------------------------------------------------------
__global__ void k_rownorm_scatter(const float* __restrict__ tmp,
                                  const int* __restrict__ batch_id,
                                  float* __restrict__ out_block,
                                  float* __restrict__ gacc) {
    int gt = blockIdx.x * blockDim.x + threadIdx.x;
    int r = gt >> 5;
    int lane = gt & 31;
    if (r >= NBLK) return;
    float4 v = *(const float4*)&tmp[(size_t)r * HID + lane * 4];
    float ss = v.x * v.x + v.y * v.y + v.z * v.z + v.w * v.w;
#pragma unroll
    for (int o = 16; o > 0; o >>= 1) ss += __shfl_xor_sync(0xffffffffu, ss, o);
    float inv = 1.0f / fmaxf(sqrtf(ss), 1e-12f);
    int g = batch_id[r];
    float4 nv = make_float4(v.x * inv, v.y * inv, v.z * inv, v.w * inv);
    *(float4*)&out_block[(size_t)r * HID + lane * 4] = nv;
    red4(&gacc[g * HID + lane * 4], nv);
}

__global__ void k_graphnorm(const float* __restrict__ gacc,
                            float* __restrict__ out_graph) {
    int gt = blockIdx.x * blockDim.x + threadIdx.x;
    int r = gt >> 5;
    int lane = gt & 31;
    if (r >= NG) return;
    float4 v = *(const float4*)&gacc[r * HID + lane * 4];
    float ss = v.x * v.x + v.y * v.y + v.z * v.z + v.w * v.w;
#pragma unroll
    for (int o = 16; o > 0; o >>= 1) ss += __shfl_xor_sync(0xffffffffu, ss, o);
    float inv = 1.0f / fmaxf(sqrtf(ss), 1e-12f);
    float4 nv = make_float4(v.x * inv, v.y * inv, v.z * inv, v.w * inv);
    *(float4*)&out_graph[r * HID + lane * 4] = nv;
}

// ---------------------------------------------------------------------------
extern "C" void kernel_launch(void* const* d_in, const int* in_sizes, int n_in,
                              void* d_out, int out_size) {
    const float* H      = (const float*)d_in[0];
    const float* Z      = (const float*)d_in[1];
    const float* W_rbf  = (const float*)d_in[2];
    const float* Wm1    = (const float*)d_in[3];
    const float* Wm2    = (const float*)d_in[4];
    const float* We     = (const float*)d_in[5];
    const float* Wupd   = (const float*)d_in[6];
    const float* W_out  = (const float*)d_in[7];
    const int*   block_id = (const int*)d_in[8];
    const int*   batch_id = (const int*)d_in[9];
    const int*   edges    = (const int*)d_in[10];

    float* out = (float*)d_out;
    float* out_Hb    = out;
    float* out_block = out + (size_t)NBLK * HID;
    float* out_graph = out + 2 * (size_t)NBLK * HID;

    void* scrv = nullptr;
    cudaGetSymbolAddress(&scrv, g_scratch);
    float* scr  = (float*)scrv;
    float* s_h    = scr + OFF_H;
    float* s_zc   = scr + OFF_ZC;
    float* s_A    = scr + OFF_A;
    float* s_B    = scr + OFF_B;
    float* s_agg  = scr + OFF_AGG;
    float* s_tab  = scr + OFF_TAB;
    float* s_Wc   = scr + OFF_WC;
    float* s_de   = scr + OFF_DE;
    float* s_gacc = scr + OFF_GACC;
    int*   s_start = (int*)(scr + OFF_START);
    int*   s_cnt   = (int*)(scr + OFF_CNT);
    int*   s_tops  = (int*)(scr + OFF_TOPS);
    int*   s_ssrc  = (int*)(scr + OFF_SSRC);

    // Wc[l] = W_rbf @ We[l], then build interpolation table
    for (int l = 0; l < NLAY; l++) {
        k_gemm<<<dim3(4, 1), 256>>>(W_rbf, We + (size_t)l * 256 * 256, nullptr,
                                    s_Wc + (size_t)l * 64 * 256, nullptr,
                                    64, 256, 256, 0, 4);
    }
    k_table<<<dim3(TABN / 4, NLAY), 256>>>(s_Wc, s_tab);

    // pooling via sorted segments
    k_bounds<<<(NATM + 256) / 256, 256>>>(block_id, s_start);
    k_pool<<<(NBLK * 32 + 255) / 256, 256>>>(H, Z, s_start, s_h, s_zc, out_Hb);

    // counting sort of edges by dst (s_cnt ends as END offsets); dist fused
    k_zero4<<<32, 256>>>((float*)s_cnt, 50016 / 4);
    k_hist<<<(NE + 255) / 256, 256>>>(edges, s_cnt);
    k_scan1<<<NTOPS, 512>>>(s_cnt, s_cnt, s_tops);
    k_scan2<<<1, 128>>>(s_tops);
    k_scan3<<<NTOPS, 512>>>(s_cnt, s_tops);
    k_scat<<<(NE + 255) / 256, 256>>>(edges, s_cnt, s_zc, s_ssrc, s_de);

    // zero graph accumulator
    k_zero4<<<8, 256>>>(s_gacc, (NG * HID) / 4);

    dim3 gridAB(8, (NBLK + 127) / 128);
    dim3 gridUpd(2, (NBLK + 127) / 128);

    for (int l = 0; l < NLAY; l++) {
        // A = h@Wm1[l], B = h@Wm2[l] in one launch
        k_gemm<<<gridAB, 256>>>(s_h, Wm1 + (size_t)l * HID * EDGEF,
                                Wm2 + (size_t)l * HID * EDGEF, s_A, s_B,
                                NBLK, EDGEF, HID, 0, 4);
        // fused edge messages + per-dst aggregation (plain stores)
        k_edge_lut<<<(NBLK * 32 + 255) / 256, 256>>>(
            s_ssrc, s_cnt, s_tab + (size_t)l * TABN * 256, s_de, s_A, s_B,
            s_agg);
        // h = h + silu(agg @ Wupd[l])
        k_gemm<<<gridUpd, 256>>>(s_agg, Wupd + (size_t)l * EDGEF * HID, nullptr,
                                 s_h, nullptr, NBLK, HID, EDGEF, 1, 2);
    }

    // block_repr = l2norm(h @ W_out)
    k_gemm<<<gridUpd, 256>>>(s_h, W_out, nullptr, s_A, nullptr,
                             NBLK, HID, HID, 0, 2);
    k_rownorm_scatter<<<(NBLK * 32 + 255) / 256, 256>>>(s_A, batch_id,
                                                        out_block, s_gacc);
    k_graphnorm<<<(NG * 32 + 255) / 256, 256>>>(s_gacc, out_graph);
}

// round 8
// speedup vs baseline: 1.1908x; 1.0075x over previous
#include <cuda_runtime.h>
#include <cuda_bf16.h>
#include <math.h>

#define NATM 200000
#define NBLK 50000
#define NE   450000
#define NG   64
#define HID  128
#define RAD  64
#define EDGEF 256
#define NLAY 3
#define TABN 2048          // table entries per layer, spacing 1/256 over [0,8)
#define TABSCALE 256.0f

// ---- scratch layout (single __device__ buffer, floats) ----
static const size_t OFF_H     = 0;          // [NBLK*128]
static const size_t OFF_ZC    = 6400000;    // [NBLK*4] z0,z1,z2,cnt
static const size_t OFF_A     = 6600000;    // [NBLK*256]
static const size_t OFF_B     = 19400000;   // [NBLK*256]
static const size_t OFF_AGG   = 32200000;   // [NBLK*256]
static const size_t OFF_TAB   = 45000000;   // [3*2048*256]
static const size_t OFF_WC    = 46572864;   // [3*64*256]
static const size_t OFF_DE    = 46622016;   // [NE] (pre-scaled by TABSCALE)
static const size_t OFF_GACC  = 47072016;   // [64*128]
static const size_t OFF_START = 47080208;   // int[NBLK+1]
static const size_t OFF_CNT   = 47130224;   // int[NBLK] (becomes end offsets)
static const size_t OFF_TOPS  = 47180240;   // int[128]
static const size_t OFF_SSRC  = 47180368;   // int[NE]
static const size_t SCR_TOTAL = 47630368;

__device__ __align__(16) float g_scratch[SCR_TOTAL];

#define NTOPS 98   // ceil(NBLK/512)

__device__ __forceinline__ float silu_f(float x) {
    return x / (1.0f + __expf(-x));
}

__device__ __forceinline__ unsigned cvt_tf32(float f) {
    unsigned u;
    asm("cvt.rna.tf32.f32 %0, %1;" : "=r"(u) : "f"(f));
    return u;
}

__device__ __forceinline__ void mma_tf32(float* c, const unsigned* a,
                                         const unsigned* b) {
    asm volatile(
        "mma.sync.aligned.m16n8k8.row.col.f32.tf32.tf32.f32 "
        "{%0,%1,%2,%3}, {%4,%5,%6,%7}, {%8,%9}, {%0,%1,%2,%3};"
        : "+f"(c[0]), "+f"(c[1]), "+f"(c[2]), "+f"(c[3])
        : "r"(a[0]), "r"(a[1]), "r"(a[2]), "r"(a[3]), "r"(b[0]), "r"(b[1]));
}

__device__ __forceinline__ void red4(float* p, float4 v) {
    asm volatile("red.global.add.v4.f32 [%0], {%1,%2,%3,%4};"
                 :: "l"(p), "f"(v.x), "f"(v.y), "f"(v.z), "f"(v.w)
                 : "memory");
}

// ---------------------------------------------------------------------------
__global__ void k_zero4(float* __restrict__ p, int n4) {
    float4 z = make_float4(0.f, 0.f, 0.f, 0.f);
    for (int i = blockIdx.x * blockDim.x + threadIdx.x; i < n4;
         i += gridDim.x * blockDim.x) {
        ((float4*)p)[i] = z;
    }
}

// ---------------------------------------------------------------------------
// segment boundaries of sorted block_id
// ---------------------------------------------------------------------------
__global__ void k_bounds(const int* __restrict__ bid, int* __restrict__ start) {
    int a = blockIdx.x * blockDim.x + threadIdx.x;
    if (a > NATM) return;
    if (a == 0) {
        int c = bid[0];
        for (int b = 0; b <= c; b++) start[b] = 0;
    } else if (a == NATM) {
        int p = bid[NATM - 1];
        for (int b = p + 1; b <= NBLK; b++) start[b] = NATM;
    } else {
        int p = bid[a - 1], c = bid[a];
        for (int b = p + 1; b <= c; b++) start[b] = a;
    }
}

// ---------------------------------------------------------------------------
// segment-mean pooling: one warp per block
// ---------------------------------------------------------------------------
__global__ void k_pool(const float* __restrict__ H, const float* __restrict__ Z,
                       const int* __restrict__ start, float* __restrict__ h,
                       float* __restrict__ zc, float* __restrict__ outHb) {
    int gt = blockIdx.x * blockDim.x + threadIdx.x;
    int b = gt >> 5;
    int lane = gt & 31;
    if (b >= NBLK) return;
    int lo = start[b], hi = start[b + 1];
    float4 hs = make_float4(0.f, 0.f, 0.f, 0.f);
    for (int a = lo; a < hi; a++) {
        float4 v = *(const float4*)&H[(size_t)a * HID + lane * 4];
        hs.x += v.x; hs.y += v.y; hs.z += v.z; hs.w += v.w;
    }
    float zx = 0.f, zy = 0.f, zz = 0.f;
    for (int a = lo + lane; a < hi; a += 32) {
        zx += Z[a * 3 + 0]; zy += Z[a * 3 + 1]; zz += Z[a * 3 + 2];
    }
#pragma unroll
    for (int o = 16; o > 0; o >>= 1) {
        zx += __shfl_xor_sync(0xffffffffu, zx, o);
        zy += __shfl_xor_sync(0xffffffffu, zy, o);
        zz += __shfl_xor_sync(0xffffffffu, zz, o);
    }
    float cnt = (float)(hi - lo);
    float inv = 1.0f / fmaxf(cnt, 1.0f);
    hs.x *= inv; hs.y *= inv; hs.z *= inv; hs.w *= inv;
    *(float4*)&h[(size_t)b * HID + lane * 4] = hs;
    *(float4*)&outHb[(size_t)b * HID + lane * 4] = hs;
    if (lane == 0) {
        zc[b * 4 + 0] = zx * inv;
        zc[b * 4 + 1] = zy * inv;
        zc[b * 4 + 2] = zz * inv;
        zc[b * 4 + 3] = cnt;
    }
}

// ---------------------------------------------------------------------------
// counting sort of edges by dst (distance computed during scatter)
// ---------------------------------------------------------------------------
__global__ void k_hist(const int* __restrict__ edges, int* __restrict__ cnt) {
    int e = blockIdx.x * blockDim.x + threadIdx.x;
    if (e < NE) atomicAdd(&cnt[edges[NE + e]], 1);
}

__global__ void k_scan1(const int* __restrict__ cnt, int* __restrict__ offs,
                        int* __restrict__ tops) {
    __shared__ int sh[512];
    int i = blockIdx.x * 512 + threadIdx.x;
    int v = (i < NBLK) ? cnt[i] : 0;
    sh[threadIdx.x] = v;
    __syncthreads();
#pragma unroll
    for (int off = 1; off < 512; off <<= 1) {
        int t = 0;
        if (threadIdx.x >= off) t = sh[threadIdx.x - off];
        __syncthreads();
        if (threadIdx.x >= off) sh[threadIdx.x] += t;
        __syncthreads();
    }
    if (i < NBLK) offs[i] = sh[threadIdx.x] - v;
    if (threadIdx.x == 511) tops[blockIdx.x] = sh[511];
}

__global__ void k_scan2(int* __restrict__ tops) {
    __shared__ int sh[128];
    int v = (threadIdx.x < NTOPS) ? tops[threadIdx.x] : 0;
    sh[threadIdx.x] = v;
    __syncthreads();
#pragma unroll
    for (int off = 1; off < 128; off <<= 1) {
        int t = 0;
        if (threadIdx.x >= off) t = sh[threadIdx.x - off];
        __syncthreads();
        if (threadIdx.x >= off) sh[threadIdx.x] += t;
        __syncthreads();
    }
    if (threadIdx.x < NTOPS) tops[threadIdx.x] = sh[threadIdx.x] - v;
}

__global__ void k_scan3(int* __restrict__ offs, const int* __restrict__ tops) {
    int i = blockIdx.x * 512 + threadIdx.x;
    if (i < NBLK) offs[i] += tops[blockIdx.x];
}

// scatter + per-edge scaled distance in sorted position
__global__ void k_scat(const int* __restrict__ edges, int* __restrict__ offs,
                       const float* __restrict__ zc, int* __restrict__ ssrc,
                       float* __restrict__ de) {
    int e = blockIdx.x * blockDim.x + threadIdx.x;
    if (e >= NE) return;
    int s = edges[e];
    int d = edges[NE + e];
    int pos = atomicAdd(&offs[d], 1);
    float dx = zc[s * 4 + 0] - zc[d * 4 + 0];
    float dy = zc[s * 4 + 1] - zc[d * 4 + 1];
    float dz = zc[s * 4 + 2] - zc[d * 4 + 2];
    ssrc[pos] = s;
    de[pos] = sqrtf(dx * dx + dy * dy + dz * dz + 1e-12f) * TABSCALE;
}
// after k_scat, offs[d] holds the END offset of dst-segment d.

// ---------------------------------------------------------------------------
// build lookup table T[l][g][j] = rbf(g/256) @ Wc[l]
// grid (TABN/4, 3), 256 threads; 4 grid points share each W read.
// ---------------------------------------------------------------------------
__global__ void k_table(const float* __restrict__ Wc, float* __restrict__ T) {
    __shared__ float rb[4][64];
    int g0 = blockIdx.x * 4, l = blockIdx.y;
    int tid = threadIdx.x;
    {
        int gi = tid >> 6;      // 0..3
        int k = tid & 63;
        float dd = (float)(g0 + gi) * (1.0f / TABSCALE)
                 - (6.0f / 63.0f) * (float)k;
        rb[gi][k] = __expf(-10.0f * dd * dd);
    }
    __syncthreads();
    const float* W = Wc + (size_t)l * 64 * 256;
    float acc0 = 0.f, acc1 = 0.f, acc2 = 0.f, acc3 = 0.f;
#pragma unroll 16
    for (int k = 0; k < 64; k++) {
        float w = W[k * 256 + tid];
        acc0 += rb[0][k] * w;
        acc1 += rb[1][k] * w;
        acc2 += rb[2][k] * w;
        acc3 += rb[3][k] * w;
    }
    float* out = T + ((size_t)l * TABN + g0) * 256 + tid;
    out[0]   = acc0;
    out[256] = acc1;
    out[512] = acc2;
    out[768] = acc3;
}

// ---------------------------------------------------------------------------
// tf32 tensor GEMM, double-buffered: C[M,N] = A[M,K] @ B[K,N]
// BM=128 BN=64 BK=32, 256 threads. block.x >= ntiles0 -> (B1,C1).
// epi==1: C += silu(acc). Requires K%32==0, N%64==0.
// ---------------------------------------------------------------------------
__global__ void __launch_bounds__(256)
k_gemm(const float* __restrict__ A, const float* __restrict__ B0,
       const float* __restrict__ B1, float* __restrict__ C0,
       float* __restrict__ C1, int M, int N, int K, int epi, int ntiles0) {
    __shared__ unsigned As[128 * 36];
    __shared__ unsigned Bs[32 * 68];
    int tid = threadIdx.x;
    int warp = tid >> 5, lane = tid & 31;
    int gid = lane >> 2, tig = lane & 3;
    int wm = (warp & 3) * 32, wn = (warp >> 2) * 32;
    int rowBase = blockIdx.y * 128;
    int bx = blockIdx.x;
    const float* B = B0;
    float* C = C0;
    if (bx >= ntiles0) { B = B1; C = C1; bx -= ntiles0; }
    int colBase = bx * 64;

    int ar = tid >> 3, ac = (tid & 7) * 4;
    int br = tid >> 4, bc = (tid & 15) * 4;

    float4 av[4], bv[2];
#pragma unroll
    for (int i = 0; i < 4; i++) {
        int r = rowBase + ar + i * 32;
        av[i] = (r < M) ? *(const float4*)&A[(size_t)r * K + ac]
                        : make_float4(0.f, 0.f, 0.f, 0.f);
    }
#pragma unroll
    for (int i = 0; i < 2; i++)
        bv[i] = *(const float4*)&B[(size_t)(br + i * 16) * N + colBase + bc];

    float acc[2][4][4];
#pragma unroll
    for (int mt = 0; mt < 2; mt++)
#pragma unroll
        for (int nn = 0; nn < 4; nn++)
#pragma unroll
            for (int q = 0; q < 4; q++) acc[mt][nn][q] = 0.f;

    for (int k0 = 0; k0 < K; k0 += 32) {
#pragma unroll
        for (int i = 0; i < 4; i++) {
            uint4 u;
            u.x = cvt_tf32(av[i].x); u.y = cvt_tf32(av[i].y);
            u.z = cvt_tf32(av[i].z); u.w = cvt_tf32(av[i].w);
            *(uint4*)&As[(ar + i * 32) * 36 + ac] = u;
        }
#pragma unroll
        for (int i = 0; i < 2; i++) {
            uint4 u;
            u.x = cvt_tf32(bv[i].x); u.y = cvt_tf32(bv[i].y);
            u.z = cvt_tf32(bv[i].z); u.w = cvt_tf32(bv[i].w);
            *(uint4*)&Bs[(br + i * 16) * 68 + bc] = u;
        }
        __syncthreads();
        if (k0 + 32 < K) {
#pragma unroll
            for (int i = 0; i < 4; i++) {
                int r = rowBase + ar + i * 32;
                av[i] = (r < M)
                    ? *(const float4*)&A[(size_t)r * K + k0 + 32 + ac]
                    : make_float4(0.f, 0.f, 0.f, 0.f);
            }
#pragma unroll
            for (int i = 0; i < 2; i++)
                bv[i] = *(const float4*)
                    &B[(size_t)(k0 + 32 + br + i * 16) * N + colBase + bc];
        }
#pragma unroll
        for (int kk = 0; kk < 4; kk++) {
            unsigned a[2][4], b[4][2];
#pragma unroll
            for (int mt = 0; mt < 2; mt++) {
                int r = wm + mt * 16 + gid;
                a[mt][0] = As[r * 36 + kk * 8 + tig];
                a[mt][1] = As[(r + 8) * 36 + kk * 8 + tig];
                a[mt][2] = As[r * 36 + kk * 8 + tig + 4];
                a[mt][3] = As[(r + 8) * 36 + kk * 8 + tig + 4];
            }
#pragma unroll
            for (int nn = 0; nn < 4; nn++) {
                b[nn][0] = Bs[(kk * 8 + tig) * 68 + wn + nn * 8 + gid];
                b[nn][1] = Bs[(kk * 8 + tig + 4) * 68 + wn + nn * 8 + gid];
            }
#pragma unroll
            for (int mt = 0; mt < 2; mt++)
#pragma unroll
                for (int nn = 0; nn < 4; nn++)
                    mma_tf32(acc[mt][nn], a[mt], b[nn]);
        }
        __syncthreads();
    }

#pragma unroll
    for (int mt = 0; mt < 2; mt++) {
#pragma unroll
        for (int nn = 0; nn < 4; nn++) {
            int r0 = rowBase + wm + mt * 16 + gid;
            int r1 = r0 + 8;
            int c = colBase + wn + nn * 8 + 2 * tig;
            if (r0 < M) {
                size_t idx = (size_t)r0 * N + c;
                if (epi == 1) {
                    C[idx]     += silu_f(acc[mt][nn][0]);
                    C[idx + 1] += silu_f(acc[mt][nn][1]);
                } else {
                    C[idx]     = acc[mt][nn][0];
                    C[idx + 1] = acc[mt][nn][1];
                }
            }
            if (r1 < M) {
                size_t idx = (size_t)r1 * N + c;
                if (epi == 1) {
                    C[idx]     += silu_f(acc[mt][nn][2]);
                    C[idx + 1] += silu_f(acc[mt][nn][3]);
                } else {
                    C[idx]     = acc[mt][nn][2];
                    C[idx + 1] = acc[mt][nn][3];
                }
            }
        }
    }
}

// ---------------------------------------------------------------------------
// edge+aggregate kernel: TWO warps per dst block (128 cols each).
// agg[d] = sum_{e in seg(d)} silu(A[src_e] + B[d] + lerp(T, de[e]))
// Plain stores (no atomics, no pre-zero). de pre-scaled by TABSCALE.
// ---------------------------------------------------------------------------
__global__ void __launch_bounds__(256)
k_edge_lut(const int* __restrict__ ssrc, const int* __restrict__ eend,
           const float* __restrict__ Tl, const float* __restrict__ de,
           const float* __restrict__ Ag, const float* __restrict__ Bg,
           float* __restrict__ agg) {
    int gw = (blockIdx.x * blockDim.x + threadIdx.x) >> 5;
    int d = gw >> 1;
    int half = gw & 1;
    int lane = threadIdx.x & 31;
    if (d >= NBLK) return;
    int lo = (d > 0) ? eend[d - 1] : 0;
    int hi = eend[d];
    int c = half * 128 + lane * 4;

    float4 acc = make_float4(0.f, 0.f, 0.f, 0.f);

    if (lo < hi) {
        float4 b = *(const float4*)&Bg[(size_t)d * 256 + c];
        const float maxT = (float)(TABN - 2) + 0.999f;
        for (int e = lo; e < hi; e++) {
            int s = ssrc[e];
            float t = fminf(de[e], maxT);
            int it = (int)t;
            float f = t - (float)it;
            const float* r0 = Tl + (size_t)it * 256;
            float4 a  = *(const float4*)&Ag[(size_t)s * 256 + c];
            float4 u0 = *(const float4*)&r0[c];
            float4 u1 = *(const float4*)&r0[256 + c];
            acc.x += silu_f(a.x + b.x + u0.x + f * (u1.x - u0.x));
            acc.y += silu_f(a.y + b.y + u0.y + f * (u1.y - u0.y));
            acc.z += silu_f(a.z + b.z + u0.z + f * (u1.z - u0.z));
            acc.w += silu_f(a.w + b.w + u0.w + f * (u1.w - u0.w));
        }
    }
    *(float4*)&agg[(size_t)d * 256 + c] = acc;
}

// ---------------------------------------------------------------------------
__global__ void k_rownorm_scatter(const float* __restrict__ tmp,
                                  const int* __restrict__ batch_id,
                                  float* __restrict__ out_block,
                                  float* __restrict__ gacc) {
    int gt = blockIdx.x * blockDim.x + threadIdx.x;
    int r = gt >> 5;
    int lane = gt & 31;
    if (r >= NBLK) return;
    float4 v = *(const float4*)&tmp[(size_t)r * HID + lane * 4];
    float ss = v.x * v.x + v.y * v.y + v.z * v.z + v.w * v.w;
#pragma unroll
    for (int o = 16; o > 0; o >>= 1) ss += __shfl_xor_sync(0xffffffffu, ss, o);
    float inv = 1.0f / fmaxf(sqrtf(ss), 1e-12f);
    int g = batch_id[r];
    float4 nv = make_float4(v.x * inv, v.y * inv, v.z * inv, v.w * inv);
    *(float4*)&out_block[(size_t)r * HID + lane * 4] = nv;
    red4(&gacc[g * HID + lane * 4], nv);
}

__global__ void k_graphnorm(const float* __restrict__ gacc,
                            float* __restrict__ out_graph) {
    int gt = blockIdx.x * blockDim.x + threadIdx.x;
    int r = gt >> 5;
    int lane = gt & 31;
    if (r >= NG) return;
    float4 v = *(const float4*)&gacc[r * HID + lane * 4];
    float ss = v.x * v.x + v.y * v.y + v.z * v.z + v.w * v.w;
#pragma unroll
    for (int o = 16; o > 0; o >>= 1) ss += __shfl_xor_sync(0xffffffffu, ss, o);
    float inv = 1.0f / fmaxf(sqrtf(ss), 1e-12f);
    float4 nv = make_float4(v.x * inv, v.y * inv, v.z * inv, v.w * inv);
    *(float4*)&out_graph[r * HID + lane * 4] = nv;
}

// ---------------------------------------------------------------------------
extern "C" void kernel_launch(void* const* d_in, const int* in_sizes, int n_in,
                              void* d_out, int out_size) {
    const float* H      = (const float*)d_in[0];
    const float* Z      = (const float*)d_in[1];
    const float* W_rbf  = (const float*)d_in[2];
    const float* Wm1    = (const float*)d_in[3];
    const float* Wm2    = (const float*)d_in[4];
    const float* We     = (const float*)d_in[5];
    const float* Wupd   = (const float*)d_in[6];
    const float* W_out  = (const float*)d_in[7];
    const int*   block_id = (const int*)d_in[8];
    const int*   batch_id = (const int*)d_in[9];
    const int*   edges    = (const int*)d_in[10];

    float* out = (float*)d_out;
    float* out_Hb    = out;
    float* out_block = out + (size_t)NBLK * HID;
    float* out_graph = out + 2 * (size_t)NBLK * HID;

    void* scrv = nullptr;
    cudaGetSymbolAddress(&scrv, g_scratch);
    float* scr  = (float*)scrv;
    float* s_h    = scr + OFF_H;
    float* s_zc   = scr + OFF_ZC;
    float* s_A    = scr + OFF_A;
    float* s_B    = scr + OFF_B;
    float* s_agg  = scr + OFF_AGG;
    float* s_tab  = scr + OFF_TAB;
    float* s_Wc   = scr + OFF_WC;
    float* s_de   = scr + OFF_DE;
    float* s_gacc = scr + OFF_GACC;
    int*   s_start = (int*)(scr + OFF_START);
    int*   s_cnt   = (int*)(scr + OFF_CNT);
    int*   s_tops  = (int*)(scr + OFF_TOPS);
    int*   s_ssrc  = (int*)(scr + OFF_SSRC);

    dim3 gridAB(8, (NBLK + 127) / 128);
    dim3 gridUpd(2, (NBLK + 127) / 128);

    // --- launches ordered so #6 (ncu -s 5) is the layer-0 A/B GEMM ---
    k_bounds<<<(NATM + 256) / 256, 256>>>(block_id, s_start);                 // 1
    k_pool<<<(NBLK * 32 + 255) / 256, 256>>>(H, Z, s_start, s_h, s_zc, out_Hb); // 2
    for (int l = 0; l < NLAY; l++) {                                          // 3-5
        k_gemm<<<dim3(4, 1), 256>>>(W_rbf, We + (size_t)l * 256 * 256, nullptr,
                                    s_Wc + (size_t)l * 64 * 256, nullptr,
                                    64, 256, 256, 0, 4);
    }
    // layer-0 A/B GEMM (launch #6 — profiled)
    k_gemm<<<gridAB, 256>>>(s_h, Wm1, Wm2, s_A, s_B, NBLK, EDGEF, HID, 0, 4);

    // table + edge sort + misc (all complete before edge kernel 0)
    k_table<<<dim3(TABN / 4, NLAY), 256>>>(s_Wc, s_tab);
    k_zero4<<<32, 256>>>((float*)s_cnt, 50016 / 4);
    k_hist<<<(NE + 255) / 256, 256>>>(edges, s_cnt);
    k_scan1<<<NTOPS, 512>>>(s_cnt, s_cnt, s_tops);
    k_scan2<<<1, 128>>>(s_tops);
    k_scan3<<<NTOPS, 512>>>(s_cnt, s_tops);
    k_scat<<<(NE + 255) / 256, 256>>>(edges, s_cnt, s_zc, s_ssrc, s_de);
    k_zero4<<<8, 256>>>(s_gacc, (NG * HID) / 4);

    for (int l = 0; l < NLAY; l++) {
        if (l > 0) {
            // A = h@Wm1[l], B = h@Wm2[l]
            k_gemm<<<gridAB, 256>>>(s_h, Wm1 + (size_t)l * HID * EDGEF,
                                    Wm2 + (size_t)l * HID * EDGEF, s_A, s_B,
                                    NBLK, EDGEF, HID, 0, 4);
        }
        // fused edge messages + per-dst aggregation (2 warps per dst)
        k_edge_lut<<<(NBLK * 64 + 255) / 256, 256>>>(
            s_ssrc, s_cnt, s_tab + (size_t)l * TABN * 256, s_de, s_A, s_B,
            s_agg);
        // h = h + silu(agg @ Wupd[l])
        k_gemm<<<gridUpd, 256>>>(s_agg, Wupd + (size_t)l * EDGEF * HID, nullptr,
                                 s_h, nullptr, NBLK, HID, EDGEF, 1, 2);
    }

    // block_repr = l2norm(h @ W_out)
    k_gemm<<<gridUpd, 256>>>(s_h, W_out, nullptr, s_A, nullptr,
                             NBLK, HID, HID, 0, 2);
    k_rownorm_scatter<<<(NBLK * 32 + 255) / 256, 256>>>(s_A, batch_id,
                                                        out_block, s_gacc);
    k_graphnorm<<<(NG * 32 + 255) / 256, 256>>>(s_gacc, out_graph);
}

// round 9
// speedup vs baseline: 1.2737x; 1.0697x over previous
#include <cuda_runtime.h>
#include <cuda_bf16.h>
#include <math.h>

#define NATM 200000
#define NBLK 50000
#define NE   450000
#define NG   64
#define HID  128
#define RAD  64
#define EDGEF 256
#define NLAY 3
#define TABN 8192          // nearest-neighbor table, spacing 1/1024 over [0,8)
#define TABSCALE 1024.0f

// ---- scratch layout (single __device__ buffer, floats) ----
static const size_t OFF_H     = 0;          // [NBLK*128]
static const size_t OFF_ZC    = 6400000;    // [NBLK*4] z0,z1,z2,cnt
static const size_t OFF_A     = 6600000;    // [NBLK*256]
static const size_t OFF_B     = 19400000;   // [NBLK*256]
static const size_t OFF_AGG   = 32200000;   // [NBLK*256]
static const size_t OFF_TAB   = 45000000;   // [3*8192*256]
static const size_t OFF_WC    = 51291456;   // [3*64*256]
static const size_t OFF_GACC  = 51340608;   // [64*128]
static const size_t OFF_START = 51348800;   // int[NBLK+1]
static const size_t OFF_CNT   = 51398816;   // int[NBLK] (becomes end offsets)
static const size_t OFF_TOPS  = 51448832;   // int[128]
static const size_t OFF_SSIT  = 51448960;   // int2[NE] (src, table row)
static const size_t SCR_TOTAL = 52349056;

__device__ __align__(16) float g_scratch[SCR_TOTAL];

#define NTOPS 98   // ceil(NBLK/512)

__device__ __forceinline__ float silu_f(float x) {
    return x / (1.0f + __expf(-x));
}

__device__ __forceinline__ unsigned cvt_tf32(float f) {
    unsigned u;
    asm("cvt.rna.tf32.f32 %0, %1;" : "=r"(u) : "f"(f));
    return u;
}

__device__ __forceinline__ void mma_tf32(float* c, const unsigned* a,
                                         const unsigned* b) {
    asm volatile(
        "mma.sync.aligned.m16n8k8.row.col.f32.tf32.tf32.f32 "
        "{%0,%1,%2,%3}, {%4,%5,%6,%7}, {%8,%9}, {%0,%1,%2,%3};"
        : "+f"(c[0]), "+f"(c[1]), "+f"(c[2]), "+f"(c[3])
        : "r"(a[0]), "r"(a[1]), "r"(a[2]), "r"(a[3]), "r"(b[0]), "r"(b[1]));
}

__device__ __forceinline__ void red4(float* p, float4 v) {
    asm volatile("red.global.add.v4.f32 [%0], {%1,%2,%3,%4};"
                 :: "l"(p), "f"(v.x), "f"(v.y), "f"(v.z), "f"(v.w)
                 : "memory");
}

// ---------------------------------------------------------------------------
__global__ void k_zero4(float* __restrict__ p, int n4) {
    float4 z = make_float4(0.f, 0.f, 0.f, 0.f);
    for (int i = blockIdx.x * blockDim.x + threadIdx.x; i < n4;
         i += gridDim.x * blockDim.x) {
        ((float4*)p)[i] = z;
    }
}

// ---------------------------------------------------------------------------
// segment boundaries of sorted block_id
// ---------------------------------------------------------------------------
__global__ void k_bounds(const int* __restrict__ bid, int* __restrict__ start) {
    int a = blockIdx.x * blockDim.x + threadIdx.x;
    if (a > NATM) return;
    if (a == 0) {
        int c = bid[0];
        for (int b = 0; b <= c; b++) start[b] = 0;
    } else if (a == NATM) {
        int p = bid[NATM - 1];
        for (int b = p + 1; b <= NBLK; b++) start[b] = NATM;
    } else {
        int p = bid[a - 1], c = bid[a];
        for (int b = p + 1; b <= c; b++) start[b] = a;
    }
}

// ---------------------------------------------------------------------------
// segment-mean pooling: one warp per block
// ---------------------------------------------------------------------------
__global__ void k_pool(const float* __restrict__ H, const float* __restrict__ Z,
                       const int* __restrict__ start, float* __restrict__ h,
                       float* __restrict__ zc, float* __restrict__ outHb) {
    int gt = blockIdx.x * blockDim.x + threadIdx.x;
    int b = gt >> 5;
    int lane = gt & 31;
    if (b >= NBLK) return;
    int lo = start[b], hi = start[b + 1];
    float4 hs = make_float4(0.f, 0.f, 0.f, 0.f);
    for (int a = lo; a < hi; a++) {
        float4 v = *(const float4*)&H[(size_t)a * HID + lane * 4];
        hs.x += v.x; hs.y += v.y; hs.z += v.z; hs.w += v.w;
    }
    float zx = 0.f, zy = 0.f, zz = 0.f;
    for (int a = lo + lane; a < hi; a += 32) {
        zx += Z[a * 3 + 0]; zy += Z[a * 3 + 1]; zz += Z[a * 3 + 2];
    }
#pragma unroll
    for (int o = 16; o > 0; o >>= 1) {
        zx += __shfl_xor_sync(0xffffffffu, zx, o);
        zy += __shfl_xor_sync(0xffffffffu, zy, o);
        zz += __shfl_xor_sync(0xffffffffu, zz, o);
    }
    float cnt = (float)(hi - lo);
    float inv = 1.0f / fmaxf(cnt, 1.0f);
    hs.x *= inv; hs.y *= inv; hs.z *= inv; hs.w *= inv;
    *(float4*)&h[(size_t)b * HID + lane * 4] = hs;
    *(float4*)&outHb[(size_t)b * HID + lane * 4] = hs;
    if (lane == 0) {
        zc[b * 4 + 0] = zx * inv;
        zc[b * 4 + 1] = zy * inv;
        zc[b * 4 + 2] = zz * inv;
        zc[b * 4 + 3] = cnt;
    }
}

// ---------------------------------------------------------------------------
// counting sort of edges by dst
// ---------------------------------------------------------------------------
__global__ void k_hist(const int* __restrict__ edges, int* __restrict__ cnt) {
    int e = blockIdx.x * blockDim.x + threadIdx.x;
    if (e < NE) atomicAdd(&cnt[edges[NE + e]], 1);
}

__global__ void k_scan1(const int* __restrict__ cnt, int* __restrict__ offs,
                        int* __restrict__ tops) {
    __shared__ int sh[512];
    int i = blockIdx.x * 512 + threadIdx.x;
    int v = (i < NBLK) ? cnt[i] : 0;
    sh[threadIdx.x] = v;
    __syncthreads();
#pragma unroll
    for (int off = 1; off < 512; off <<= 1) {
        int t = 0;
        if (threadIdx.x >= off) t = sh[threadIdx.x - off];
        __syncthreads();
        if (threadIdx.x >= off) sh[threadIdx.x] += t;
        __syncthreads();
    }
    if (i < NBLK) offs[i] = sh[threadIdx.x] - v;
    if (threadIdx.x == 511) tops[blockIdx.x] = sh[511];
}

__global__ void k_scan2(int* __restrict__ tops) {
    __shared__ int sh[128];
    int v = (threadIdx.x < NTOPS) ? tops[threadIdx.x] : 0;
    sh[threadIdx.x] = v;
    __syncthreads();
#pragma unroll
    for (int off = 1; off < 128; off <<= 1) {
        int t = 0;
        if (threadIdx.x >= off) t = sh[threadIdx.x - off];
        __syncthreads();
        if (threadIdx.x >= off) sh[threadIdx.x] += t;
        __syncthreads();
    }
    if (threadIdx.x < NTOPS) tops[threadIdx.x] = sh[threadIdx.x] - v;
}

__global__ void k_scan3(int* __restrict__ offs, const int* __restrict__ tops) {
    int i = blockIdx.x * 512 + threadIdx.x;
    if (i < NBLK) offs[i] += tops[blockIdx.x];
}

// scatter: sorted position gets (src, nearest table row index)
__global__ void k_scat(const int* __restrict__ edges, int* __restrict__ offs,
                       const float* __restrict__ zc, int2* __restrict__ ssit) {
    int e = blockIdx.x * blockDim.x + threadIdx.x;
    if (e >= NE) return;
    int s = edges[e];
    int d = edges[NE + e];
    int pos = atomicAdd(&offs[d], 1);
    float dx = zc[s * 4 + 0] - zc[d * 4 + 0];
    float dy = zc[s * 4 + 1] - zc[d * 4 + 1];
    float dz = zc[s * 4 + 2] - zc[d * 4 + 2];
    float dd = sqrtf(dx * dx + dy * dy + dz * dz + 1e-12f);
    int it = (int)(dd * TABSCALE + 0.5f);
    if (it > TABN - 1) it = TABN - 1;
    ssit[pos] = make_int2(s, it);
}
// after k_scat, offs[d] holds the END offset of dst-segment d.

// ---------------------------------------------------------------------------
// build lookup table T[l][g][j] = rbf(g/1024) @ Wc[l]
// grid (TABN/8, 3), 256 threads; 8 grid points share each W read.
// ---------------------------------------------------------------------------
__global__ void k_table(const float* __restrict__ Wc, float* __restrict__ T) {
    __shared__ float rb[8][64];
    int g0 = blockIdx.x * 8, l = blockIdx.y;
    int tid = threadIdx.x;
    for (int i = tid; i < 8 * 64; i += 256) {
        int gi = i >> 6;
        int k = i & 63;
        float dd = (float)(g0 + gi) * (1.0f / TABSCALE)
                 - (6.0f / 63.0f) * (float)k;
        rb[gi][k] = __expf(-10.0f * dd * dd);
    }
    __syncthreads();
    const float* W = Wc + (size_t)l * 64 * 256;
    float acc[8];
#pragma unroll
    for (int gi = 0; gi < 8; gi++) acc[gi] = 0.f;
#pragma unroll 8
    for (int k = 0; k < 64; k++) {
        float w = W[k * 256 + tid];
#pragma unroll
        for (int gi = 0; gi < 8; gi++) acc[gi] += rb[gi][k] * w;
    }
    float* out = T + ((size_t)l * TABN + g0) * 256 + tid;
#pragma unroll
    for (int gi = 0; gi < 8; gi++) out[gi * 256] = acc[gi];
}

// ---------------------------------------------------------------------------
// tf32 tensor GEMM, double-buffered: C[M,N] = A[M,K] @ B[K,N]
// BM=128 BN=64 BK=32, 256 threads. block.x >= ntiles0 -> (B1,C1).
// epi==1: C += silu(acc). Requires K%32==0, N%64==0.
// ---------------------------------------------------------------------------
__global__ void __launch_bounds__(256)
k_gemm(const float* __restrict__ A, const float* __restrict__ B0,
       const float* __restrict__ B1, float* __restrict__ C0,
       float* __restrict__ C1, int M, int N, int K, int epi, int ntiles0) {
    __shared__ unsigned As[128 * 36];
    __shared__ unsigned Bs[32 * 68];
    int tid = threadIdx.x;
    int warp = tid >> 5, lane = tid & 31;
    int gid = lane >> 2, tig = lane & 3;
    int wm = (warp & 3) * 32, wn = (warp >> 2) * 32;
    int rowBase = blockIdx.y * 128;
    int bx = blockIdx.x;
    const float* B = B0;
    float* C = C0;
    if (bx >= ntiles0) { B = B1; C = C1; bx -= ntiles0; }
    int colBase = bx * 64;

    int ar = tid >> 3, ac = (tid & 7) * 4;
    int br = tid >> 4, bc = (tid & 15) * 4;

    float4 av[4], bv[2];
#pragma unroll
    for (int i = 0; i < 4; i++) {
        int r = rowBase + ar + i * 32;
        av[i] = (r < M) ? *(const float4*)&A[(size_t)r * K + ac]
                        : make_float4(0.f, 0.f, 0.f, 0.f);
    }
#pragma unroll
    for (int i = 0; i < 2; i++)
        bv[i] = *(const float4*)&B[(size_t)(br + i * 16) * N + colBase + bc];

    float acc[2][4][4];
#pragma unroll
    for (int mt = 0; mt < 2; mt++)
#pragma unroll
        for (int nn = 0; nn < 4; nn++)
#pragma unroll
            for (int q = 0; q < 4; q++) acc[mt][nn][q] = 0.f;

    for (int k0 = 0; k0 < K; k0 += 32) {
#pragma unroll
        for (int i = 0; i < 4; i++) {
            uint4 u;
            u.x = cvt_tf32(av[i].x); u.y = cvt_tf32(av[i].y);
            u.z = cvt_tf32(av[i].z); u.w = cvt_tf32(av[i].w);
            *(uint4*)&As[(ar + i * 32) * 36 + ac] = u;
        }
#pragma unroll
        for (int i = 0; i < 2; i++) {
            uint4 u;
            u.x = cvt_tf32(bv[i].x); u.y = cvt_tf32(bv[i].y);
            u.z = cvt_tf32(bv[i].z); u.w = cvt_tf32(bv[i].w);
            *(uint4*)&Bs[(br + i * 16) * 68 + bc] = u;
        }
        __syncthreads();
        if (k0 + 32 < K) {
#pragma unroll
            for (int i = 0; i < 4; i++) {
                int r = rowBase + ar + i * 32;
                av[i] = (r < M)
                    ? *(const float4*)&A[(size_t)r * K + k0 + 32 + ac]
                    : make_float4(0.f, 0.f, 0.f, 0.f);
            }
#pragma unroll
            for (int i = 0; i < 2; i++)
                bv[i] = *(const float4*)
                    &B[(size_t)(k0 + 32 + br + i * 16) * N + colBase + bc];
        }
#pragma unroll
        for (int kk = 0; kk < 4; kk++) {
            unsigned a[2][4], b[4][2];
#pragma unroll
            for (int mt = 0; mt < 2; mt++) {
                int r = wm + mt * 16 + gid;
                a[mt][0] = As[r * 36 + kk * 8 + tig];
                a[mt][1] = As[(r + 8) * 36 + kk * 8 + tig];
                a[mt][2] = As[r * 36 + kk * 8 + tig + 4];
                a[mt][3] = As[(r + 8) * 36 + kk * 8 + tig + 4];
            }
#pragma unroll
            for (int nn = 0; nn < 4; nn++) {
                b[nn][0] = Bs[(kk * 8 + tig) * 68 + wn + nn * 8 + gid];
                b[nn][1] = Bs[(kk * 8 + tig + 4) * 68 + wn + nn * 8 + gid];
            }
#pragma unroll
            for (int mt = 0; mt < 2; mt++)
#pragma unroll
                for (int nn = 0; nn < 4; nn++)
                    mma_tf32(acc[mt][nn], a[mt], b[nn]);
        }
        __syncthreads();
    }

#pragma unroll
    for (int mt = 0; mt < 2; mt++) {
#pragma unroll
        for (int nn = 0; nn < 4; nn++) {
            int r0 = rowBase + wm + mt * 16 + gid;
            int r1 = r0 + 8;
            int c = colBase + wn + nn * 8 + 2 * tig;
            if (r0 < M) {
                size_t idx = (size_t)r0 * N + c;
                if (epi == 1) {
                    C[idx]     += silu_f(acc[mt][nn][0]);
                    C[idx + 1] += silu_f(acc[mt][nn][1]);
                } else {
                    C[idx]     = acc[mt][nn][0];
                    C[idx + 1] = acc[mt][nn][1];
                }
            }
            if (r1 < M) {
                size_t idx = (size_t)r1 * N + c;
                if (epi == 1) {
                    C[idx]     += silu_f(acc[mt][nn][2]);
                    C[idx + 1] += silu_f(acc[mt][nn][3]);
                } else {
                    C[idx]     = acc[mt][nn][2];
                    C[idx + 1] = acc[mt][nn][3];
                }
            }
        }
    }
}

// ---------------------------------------------------------------------------
// edge+aggregate kernel: TWO warps per dst block (128 cols each).
// agg[d] = sum_{e in seg(d)} silu(A[src_e] + B[d] + T[row_e])
// Nearest-neighbor table row; (src,row) packed as int2. Plain stores.
// ---------------------------------------------------------------------------
__global__ void __launch_bounds__(256)
k_edge_lut(const int2* __restrict__ ssit, const int* __restrict__ eend,
           const float* __restrict__ Tl, const float* __restrict__ Ag,
           const float* __restrict__ Bg, float* __restrict__ agg) {
    int gw = (blockIdx.x * blockDim.x + threadIdx.x) >> 5;
    int d = gw >> 1;
    int half = gw & 1;
    int lane = threadIdx.x & 31;
    if (d >= NBLK) return;
    int lo = (d > 0) ? eend[d - 1] : 0;
    int hi = eend[d];
    int c = half * 128 + lane * 4;

    float4 acc = make_float4(0.f, 0.f, 0.f, 0.f);

    if (lo < hi) {
        float4 b = *(const float4*)&Bg[(size_t)d * 256 + c];
        for (int e = lo; e < hi; e++) {
            int2 se = ssit[e];
            float4 a = *(const float4*)&Ag[((size_t)se.x << 8) + c];
            float4 u = *(const float4*)&Tl[((size_t)se.y << 8) + c];
            acc.x += silu_f(a.x + b.x + u.x);
            acc.y += silu_f(a.y + b.y + u.y);
            acc.z += silu_f(a.z + b.z + u.z);
            acc.w += silu_f(a.w + b.w + u.w);
        }
    }
    *(float4*)&agg[(size_t)d * 256 + c] = acc;
}

// ---------------------------------------------------------------------------
__global__ void k_rownorm_scatter(const float* __restrict__ tmp,
                                  const int* __restrict__ batch_id,
                                  float* __restrict__ out_block,
                                  float* __restrict__ gacc) {
    int gt = blockIdx.x * blockDim.x + threadIdx.x;
    int r = gt >> 5;
    int lane = gt & 31;
    if (r >= NBLK) return;
    float4 v = *(const float4*)&tmp[(size_t)r * HID + lane * 4];
    float ss = v.x * v.x + v.y * v.y + v.z * v.z + v.w * v.w;
#pragma unroll
    for (int o = 16; o > 0; o >>= 1) ss += __shfl_xor_sync(0xffffffffu, ss, o);
    float inv = 1.0f / fmaxf(sqrtf(ss), 1e-12f);
    int g = batch_id[r];
    float4 nv = make_float4(v.x * inv, v.y * inv, v.z * inv, v.w * inv);
    *(float4*)&out_block[(size_t)r * HID + lane * 4] = nv;
    red4(&gacc[g * HID + lane * 4], nv);
}

__global__ void k_graphnorm(const float* __restrict__ gacc,
                            float* __restrict__ out_graph) {
    int gt = blockIdx.x * blockDim.x + threadIdx.x;
    int r = gt >> 5;
    int lane = gt & 31;
    if (r >= NG) return;
    float4 v = *(const float4*)&gacc[r * HID + lane * 4];
    float ss = v.x * v.x + v.y * v.y + v.z * v.z + v.w * v.w;
#pragma unroll
    for (int o = 16; o > 0; o >>= 1) ss += __shfl_xor_sync(0xffffffffu, ss, o);
    float inv = 1.0f / fmaxf(sqrtf(ss), 1e-12f);
    float4 nv = make_float4(v.x * inv, v.y * inv, v.z * inv, v.w * inv);
    *(float4*)&out_graph[r * HID + lane * 4] = nv;
}

// ---------------------------------------------------------------------------
extern "C" void kernel_launch(void* const* d_in, const int* in_sizes, int n_in,
                              void* d_out, int out_size) {
    const float* H      = (const float*)d_in[0];
    const float* Z      = (const float*)d_in[1];
    const float* W_rbf  = (const float*)d_in[2];
    const float* Wm1    = (const float*)d_in[3];
    const float* Wm2    = (const float*)d_in[4];
    const float* We     = (const float*)d_in[5];
    const float* Wupd   = (const float*)d_in[6];
    const float* W_out  = (const float*)d_in[7];
    const int*   block_id = (const int*)d_in[8];
    const int*   batch_id = (const int*)d_in[9];
    const int*   edges    = (const int*)d_in[10];

    float* out = (float*)d_out;
    float* out_Hb    = out;
    float* out_block = out + (size_t)NBLK * HID;
    float* out_graph = out + 2 * (size_t)NBLK * HID;

    void* scrv = nullptr;
    cudaGetSymbolAddress(&scrv, g_scratch);
    float* scr  = (float*)scrv;
    float* s_h    = scr + OFF_H;
    float* s_zc   = scr + OFF_ZC;
    float* s_A    = scr + OFF_A;
    float* s_B    = scr + OFF_B;
    float* s_agg  = scr + OFF_AGG;
    float* s_tab  = scr + OFF_TAB;
    float* s_Wc   = scr + OFF_WC;
    float* s_gacc = scr + OFF_GACC;
    int*   s_start = (int*)(scr + OFF_START);
    int*   s_cnt   = (int*)(scr + OFF_CNT);
    int*   s_tops  = (int*)(scr + OFF_TOPS);
    int2*  s_ssit  = (int2*)(scr + OFF_SSIT);

    dim3 gridAB(8, (NBLK + 127) / 128);
    dim3 gridUpd(2, (NBLK + 127) / 128);

    // --- order: Wc GEMMs (0-2), bounds (3), pool (4), AB GEMM (5 = ncu slot)
    for (int l = 0; l < NLAY; l++) {
        k_gemm<<<dim3(4, 1), 256>>>(W_rbf, We + (size_t)l * 256 * 256, nullptr,
                                    s_Wc + (size_t)l * 64 * 256, nullptr,
                                    64, 256, 256, 0, 4);
    }
    k_bounds<<<(NATM + 256) / 256, 256>>>(block_id, s_start);
    k_pool<<<(NBLK * 32 + 255) / 256, 256>>>(H, Z, s_start, s_h, s_zc, out_Hb);
    // layer-0 A/B GEMM (launch index 5 — profiled)
    k_gemm<<<gridAB, 256>>>(s_h, Wm1, Wm2, s_A, s_B, NBLK, EDGEF, HID, 0, 4);

    // table + edge sort + misc (all complete before edge kernel 0)
    k_table<<<dim3(TABN / 8, NLAY), 256>>>(s_Wc, s_tab);
    k_zero4<<<32, 256>>>((float*)s_cnt, 50016 / 4);
    k_hist<<<(NE + 255) / 256, 256>>>(edges, s_cnt);
    k_scan1<<<NTOPS, 512>>>(s_cnt, s_cnt, s_tops);
    k_scan2<<<1, 128>>>(s_tops);
    k_scan3<<<NTOPS, 512>>>(s_cnt, s_tops);
    k_scat<<<(NE + 255) / 256, 256>>>(edges, s_cnt, s_zc, s_ssit);
    k_zero4<<<8, 256>>>(s_gacc, (NG * HID) / 4);

    for (int l = 0; l < NLAY; l++) {
        if (l > 0) {
            k_gemm<<<gridAB, 256>>>(s_h, Wm1 + (size_t)l * HID * EDGEF,
                                    Wm2 + (size_t)l * HID * EDGEF, s_A, s_B,
                                    NBLK, EDGEF, HID, 0, 4);
        }
        // fused edge messages + per-dst aggregation (2 warps per dst)
        k_edge_lut<<<(NBLK * 64 + 255) / 256, 256>>>(
            s_ssit, s_cnt, s_tab + (size_t)l * TABN * 256, s_A, s_B, s_agg);
        // h = h + silu(agg @ Wupd[l])
        k_gemm<<<gridUpd, 256>>>(s_agg, Wupd + (size_t)l * EDGEF * HID, nullptr,
                                 s_h, nullptr, NBLK, HID, EDGEF, 1, 2);
    }

    // block_repr = l2norm(h @ W_out)
    k_gemm<<<gridUpd, 256>>>(s_h, W_out, nullptr, s_A, nullptr,
                             NBLK, HID, HID, 0, 2);
    k_rownorm_scatter<<<(NBLK * 32 + 255) / 256, 256>>>(s_A, batch_id,
                                                        out_block, s_gacc);
    k_graphnorm<<<(NG * 32 + 255) / 256, 256>>>(s_gacc, out_graph);
}